// round 15
// baseline (speedup 1.0000x reference)
#include <cuda_runtime.h>
#include <cstdint>

// Problem constants:
//   B=8, H=8, L=1024, D=64, K=49
//   x:  (B,H,L,D) fp32   = d_in[0]
//   W:  (H,D,K)   fp32   = d_in[1]
//   rp: (L,L)     int32  = d_in[2]
//   out:(B,H,L,L) fp32
// Separable structure: i = row_i*32 + col_i, j = rj*32 + cj,
//   rp[i][j] = 7*(pw(row_i-rj)+3) + (pw(col_i-cj)+3), pw in [-3,3].
#define BB 8
#define HH 8
#define LL 1024
#define DD 64
#define KK 49
#define BH (BB*HH)

#define XP 10                  // padded xst row: 8 b's + 2 pad
#define WSLOT (DD * XP)        // 640 floats per warp slot
#define NUNITS (LL * HH)       // 8192 warp-units: (i, h)
#define GRID_BLOCKS 740        // 148 SMs x 5 resident blocks

__device__ unsigned int g_ctr;

__global__ void reset_ctr_kernel() { g_ctr = 0u; }

// ---------------------------------------------------------------------------
// Fused kernel v12: persistent blocks + warp-granular work stealing.
//   Each warp loops: u = atomicAdd(g_ctr) -> unit (i = u>>3, h = u&7),
//   owns ALL 8 b's for that (i, h).
//   compute: v10's b-pair FFMA2; W via __ldg (L1/L2-resident, warp-coalesced);
//            x staged per-warp in padded-transposed smem slot.
//   gather:  v10's proven loop: per rj: 1 shfl + 8 broadcast LDS + 8 STG.32.
//   Overlay: warp's x slot is reused for the lt spill (warp-private, syncwarp).
// grid: 740 blocks x 256 thr -> exactly fills the machine; ~3 us tail.
// ---------------------------------------------------------------------------
__global__ __launch_bounds__(256, 5) void irpe_fused12_kernel(
    const float* __restrict__ x, const float* __restrict__ W,
    const int* __restrict__ rp, float* __restrict__ out)
{
    const int tid  = threadIdx.x;
    const int w    = tid >> 5;
    const int lane = tid & 31;

    __shared__ float buf[8 * WSLOT];      // 20 KB: per-warp x slot / lt overlay
    float* xw = buf + w * WSLOT;

    const int k1 = (lane < KK - 32) ? 32 + lane : KK - 1;  // clamped (junk discarded)

    for (;;) {
        unsigned u;
        if (lane == 0) u = atomicAdd(&g_ctr, 1u);
        u = __shfl_sync(0xffffffffu, u, 0);
        if (u >= NUNITS) break;

        const int i = (int)(u >> 3);
        const int h = (int)(u & 7u);
        const int row_i = i >> 5;
        const int col_i = i & 31;

        // Separable index extraction (two tiny rp reads)
        const int cidx  = __ldg(rp + (size_t)i * LL + row_i * 32 + lane) - 21;
        const int rbase = __ldg(rp + (size_t)i * LL + lane * 32 + col_i) - 3;

        // Stage x (warp-private, padded-transposed): xw[d*10 + b]
        {
            const int b  = lane >> 2;            // 0..7
            const int q0 = (lane & 3) * 4;       // 0,4,8,12
            const float* xb = x + ((size_t)(b * HH + h) * LL + i) * DD;
            #pragma unroll
            for (int n = 0; n < 4; n++) {
                const int q = q0 + n;            // 0..15
                float4 v = *(const float4*)(xb + q * 4);
                float* dst = xw + (q * 4) * XP + b;
                dst[0 * XP] = v.x;
                dst[1 * XP] = v.y;
                dst[2 * XP] = v.z;
                dst[3 * XP] = v.w;
            }
        }
        __syncwarp();

        // Compute lt for all 8 b (b-pairs packed in f32x2); W via __ldg.
        unsigned long long acc[8];
        #pragma unroll
        for (int j = 0; j < 8; j++) acc[j] = 0ull;

        const float* Wh = W + (size_t)h * DD * KK;
        #pragma unroll 16
        for (int d = 0; d < DD; d++) {
            const float w0 = __ldg(Wh + d * KK + lane);
            const float w1 = __ldg(Wh + d * KK + k1);    // junk lanes>=17, discarded
            unsigned long long wp0, wp1;
            asm("mov.b64 %0, {%1, %1};" : "=l"(wp0) : "f"(w0));
            asm("mov.b64 %0, {%1, %1};" : "=l"(wp1) : "f"(w1));
            const float* xr = xw + d * XP;               // 8B-aligned row
            const unsigned long long xa = *(const unsigned long long*)(xr);
            const unsigned long long xb = *(const unsigned long long*)(xr + 2);
            const unsigned long long xc = *(const unsigned long long*)(xr + 4);
            const unsigned long long xd = *(const unsigned long long*)(xr + 6);
            asm("fma.rn.f32x2 %0, %1, %2, %0;" : "+l"(acc[0]) : "l"(xa), "l"(wp0));
            asm("fma.rn.f32x2 %0, %1, %2, %0;" : "+l"(acc[1]) : "l"(xb), "l"(wp0));
            asm("fma.rn.f32x2 %0, %1, %2, %0;" : "+l"(acc[2]) : "l"(xc), "l"(wp0));
            asm("fma.rn.f32x2 %0, %1, %2, %0;" : "+l"(acc[3]) : "l"(xd), "l"(wp0));
            asm("fma.rn.f32x2 %0, %1, %2, %0;" : "+l"(acc[4]) : "l"(xa), "l"(wp1));
            asm("fma.rn.f32x2 %0, %1, %2, %0;" : "+l"(acc[5]) : "l"(xb), "l"(wp1));
            asm("fma.rn.f32x2 %0, %1, %2, %0;" : "+l"(acc[6]) : "l"(xc), "l"(wp1));
            asm("fma.rn.f32x2 %0, %1, %2, %0;" : "+l"(acc[7]) : "l"(xd), "l"(wp1));
        }
        __syncwarp();   // all lanes done reading xw (x data now dead)

        // Spill lt into the SAME warp-private slot: lw[b*49 + k]
        float* lw = xw;
        #pragma unroll
        for (int bp = 0; bp < 4; bp++) {
            float lo, hi;
            asm("mov.b64 {%0, %1}, %2;" : "=f"(lo), "=f"(hi) : "l"(acc[bp]));
            lw[(2 * bp)     * KK + lane] = lo;
            lw[(2 * bp + 1) * KK + lane] = hi;
            if (lane < KK - 32) {
                asm("mov.b64 {%0, %1}, %2;" : "=f"(lo), "=f"(hi) : "l"(acc[4 + bp]));
                lw[(2 * bp)     * KK + 32 + lane] = lo;
                lw[(2 * bp + 1) * KK + 32 + lane] = hi;
            }
        }
        __syncwarp();

        // Gather + streaming stores (v10 proven loop).
        // out[b*8+h][i][rj*32+lane] = lw[b*49 + rbase(rj) + cidx(lane)]
        const float* lwc = lw + cidx;
        float* dst = out + ((size_t)h * LL + i) * LL + lane;
        #pragma unroll 4
        for (int rj = 0; rj < 32; rj++) {
            const int rb = __shfl_sync(0xffffffffu, rbase, rj);
            const float* src = lwc + rb;
            #pragma unroll
            for (int b = 0; b < BB; b++) {
                const float v = src[b * KK];                   // broadcast LDS
                __stcs(dst + (size_t)b * (HH * LL * LL), v);   // coalesced STG.32
            }
            dst += 32;
        }
        __syncwarp();   // gather reads done before next unit's staging overwrites
    }
}

// ---------------------------------------------------------------------------
extern "C" void kernel_launch(void* const* d_in, const int* in_sizes, int n_in,
                              void* d_out, int out_size)
{
    const float* x  = (const float*)d_in[0];
    const float* W  = (const float*)d_in[1];
    const int*   rp = (const int*)d_in[2];
    float*       out = (float*)d_out;

    reset_ctr_kernel<<<1, 1>>>();
    irpe_fused12_kernel<<<GRID_BLOCKS, 256>>>(x, W, rp, out);
}

// round 16
// speedup vs baseline: 1.0736x; 1.0736x over previous
#include <cuda_runtime.h>
#include <cstdint>

// Problem constants:
//   B=8, H=8, L=1024, D=64, K=49
//   x:  (B,H,L,D) fp32   = d_in[0]
//   W:  (H,D,K)   fp32   = d_in[1]
//   rp: (L,L)     int32  = d_in[2]
//   out:(B,H,L,L) fp32
// Separable structure: i = row_i*32 + col_i, j = rj*32 + cj,
//   rp[i][j] = 7*(pw(row_i-rj)+3) + (pw(col_i-cj)+3), pw in [-3,3].
#define BB 8
#define HH 8
#define LL 1024
#define DD 64
#define KK 49
#define BH (BB*HH)

#define XP2 6                    // padded xst row: 4 b's + 2 pad (24B, 8B-aligned)
#define WSLOT2 (DD * XP2)        // 384 floats per warp slot (>= 4*49 lt spill)
#define UNITS_PER_H (LL * 2)     // (i, b-half) units per head = 2048
#define GRID_BLOCKS 740          // 148 SMs x 5 resident blocks

__device__ unsigned int g_ctr8[HH];

__global__ void reset_ctr_kernel()
{
    if (threadIdx.x < HH) g_ctr8[threadIdx.x] = 0u;
}

// ---------------------------------------------------------------------------
// Fused kernel v13: h-pinned persistent blocks + warp stealing of fine units.
//   Block h = blockIdx.x & 7; Ws[h] staged ONCE per block in smem.
//   Warp unit u in [0, 2048): i = u>>1, half = u&1 -> b in {half*4 .. +3}.
//   compute: b-pair FFMA2 (2 acc pairs), W from smem (conflict-free),
//            x staged per-warp padded-transposed (XP2=6).
//   gather:  v10 loop on 4 b's: per rj: 1 shfl + 4 broadcast LDS + 4 STG.32.
//   Overlay: warp slot reused for the lt spill (warp-private, syncwarp only).
// grid: 740 blocks x 256 thr.
// ---------------------------------------------------------------------------
__global__ __launch_bounds__(256, 5) void irpe_fused13_kernel(
    const float* __restrict__ x, const float* __restrict__ W,
    const int* __restrict__ rp, float* __restrict__ out)
{
    const int tid  = threadIdx.x;
    const int w    = tid >> 5;
    const int lane = tid & 31;
    const int h    = blockIdx.x & 7;

    __shared__ float Ws[DD * KK + 32];     // 12.7 KB, natural layout
    __shared__ float buf[8 * WSLOT2];      // 12.3 KB: per-warp x slot / lt overlay
    float* xw = buf + w * WSLOT2;

    // Stage W[h] once (direct coalesced copy)
    {
        const float* Wh = W + (size_t)h * DD * KK;
        #pragma unroll
        for (int t = tid; t < DD * KK; t += 256)
            Ws[t] = Wh[t];
    }
    __syncthreads();

    const int k1 = (lane < KK - 32) ? 32 + lane : KK - 1;  // clamped (junk discarded)

    for (;;) {
        unsigned u;
        if (lane == 0) u = atomicAdd(&g_ctr8[h], 1u);
        u = __shfl_sync(0xffffffffu, u, 0);
        if (u >= UNITS_PER_H) break;

        const int i    = (int)(u >> 1);
        const int half = (int)(u & 1u);        // b in {half*4 .. half*4+3}
        const int row_i = i >> 5;
        const int col_i = i & 31;

        // Separable index extraction (two tiny rp reads)
        const int cidx  = __ldg(rp + (size_t)i * LL + row_i * 32 + lane) - 21;
        const int rbase = __ldg(rp + (size_t)i * LL + lane * 32 + col_i) - 3;

        // Stage x (warp-private, padded-transposed): xw[d*6 + bl], bl = 0..3
        {
            const int bl = lane >> 3;                    // 0..3
            const int b  = half * 4 + bl;
            const int q0 = (lane & 7) * 2;               // 2 quads per lane
            const float* xb = x + ((size_t)(b * HH + h) * LL + i) * DD;
            #pragma unroll
            for (int n = 0; n < 2; n++) {
                const int q = q0 + n;                    // 0..15
                float4 v = *(const float4*)(xb + q * 4);
                float* dst = xw + (q * 4) * XP2 + bl;
                dst[0 * XP2] = v.x;
                dst[1 * XP2] = v.y;
                dst[2 * XP2] = v.z;
                dst[3 * XP2] = v.w;
            }
        }
        __syncwarp();

        // Compute lt for 4 b's: acc[p] = { lt[2p][lane], lt[2p+1][lane] },
        //                       acc[2+p] = same for k = lane+32 (lanes < 17)
        unsigned long long acc[4];
        #pragma unroll
        for (int j = 0; j < 4; j++) acc[j] = 0ull;

        #pragma unroll 16
        for (int d = 0; d < DD; d++) {
            const float w0 = Ws[d * KK + lane];          // conflict-free
            const float w1 = Ws[d * KK + k1];            // junk lanes>=17, discarded
            unsigned long long wp0, wp1;
            asm("mov.b64 %0, {%1, %1};" : "=l"(wp0) : "f"(w0));
            asm("mov.b64 %0, {%1, %1};" : "=l"(wp1) : "f"(w1));
            const float* xr = xw + d * XP2;              // 8B-aligned row
            const unsigned long long xa = *(const unsigned long long*)(xr);      // {b0,b1}
            const unsigned long long xb = *(const unsigned long long*)(xr + 2);  // {b2,b3}
            asm("fma.rn.f32x2 %0, %1, %2, %0;" : "+l"(acc[0]) : "l"(xa), "l"(wp0));
            asm("fma.rn.f32x2 %0, %1, %2, %0;" : "+l"(acc[1]) : "l"(xb), "l"(wp0));
            asm("fma.rn.f32x2 %0, %1, %2, %0;" : "+l"(acc[2]) : "l"(xa), "l"(wp1));
            asm("fma.rn.f32x2 %0, %1, %2, %0;" : "+l"(acc[3]) : "l"(xb), "l"(wp1));
        }
        __syncwarp();   // all lanes done reading xw (x data now dead)

        // Spill lt into the SAME warp-private slot: lw[bl*49 + k]
        float* lw = xw;
        #pragma unroll
        for (int p = 0; p < 2; p++) {
            float lo, hi;
            asm("mov.b64 {%0, %1}, %2;" : "=f"(lo), "=f"(hi) : "l"(acc[p]));
            lw[(2 * p)     * KK + lane] = lo;
            lw[(2 * p + 1) * KK + lane] = hi;
            if (lane < KK - 32) {
                asm("mov.b64 {%0, %1}, %2;" : "=f"(lo), "=f"(hi) : "l"(acc[2 + p]));
                lw[(2 * p)     * KK + 32 + lane] = lo;
                lw[(2 * p + 1) * KK + 32 + lane] = hi;
            }
        }
        __syncwarp();

        // Gather + streaming stores (4 b's).
        // out[(half*4+bl)*8+h][i][rj*32+lane] = lw[bl*49 + rbase(rj) + cidx(lane)]
        const float* lwc = lw + cidx;
        float* dst = out + (((size_t)(half * 4 * HH + h)) * LL + i) * LL + lane;
        #pragma unroll 4
        for (int rj = 0; rj < 32; rj++) {
            const int rb = __shfl_sync(0xffffffffu, rbase, rj);
            const float* src = lwc + rb;
            #pragma unroll
            for (int bl = 0; bl < 4; bl++) {
                const float v = src[bl * KK];                  // broadcast LDS
                __stcs(dst + (size_t)bl * (HH * LL * LL), v);  // coalesced STG.32
            }
            dst += 32;
        }
        __syncwarp();   // gather reads done before next unit's staging overwrites
    }
}

// ---------------------------------------------------------------------------
extern "C" void kernel_launch(void* const* d_in, const int* in_sizes, int n_in,
                              void* d_out, int out_size)
{
    const float* x  = (const float*)d_in[0];
    const float* W  = (const float*)d_in[1];
    const int*   rp = (const int*)d_in[2];
    float*       out = (float*)d_out;

    reset_ctr_kernel<<<1, 32>>>();
    irpe_fused13_kernel<<<GRID_BLOCKS, 256>>>(x, W, rp, out);
}

// round 17
// speedup vs baseline: 1.0853x; 1.0109x over previous
#include <cuda_runtime.h>
#include <cstdint>

// Problem constants:
//   B=8, H=8, L=1024, D=64, K=49
//   x:  (B,H,L,D) fp32   = d_in[0]
//   W:  (H,D,K)   fp32   = d_in[1]
//   rp: (L,L)     int32  = d_in[2]
//   out:(B,H,L,L) fp32
// Separable structure: i = row_i*32 + col_i, j = rj*32 + cj,
//   rp[i][j] = 7*(pw(row_i-rj)+3) + (pw(col_i-cj)+3), pw in [-3,3].
#define BB 8
#define HH 8
#define LL 1024
#define DD 64
#define KK 49
#define BH (BB*HH)

#define IPB 8              // i-rows per block (one per warp)
#define XP 12              // padded xst row: 8 b's + 4 pad (48B, 16B-aligned)
#define WSLOT (DD * XP)    // 768 floats: per-warp region in the shared overlay

// ---------------------------------------------------------------------------
// Fused kernel v14 = v10 with:
//   (a) XP=12 -> x rows 16B-aligned -> compute x-reads are 2 broadcast
//       LDS.128 per d (was 4 LDS.64): -128 MIO ops per warp-row.
//   (b) __launch_bounds__(256, 6): 6 resident blocks/SM (was 5) to attack
//       the latency bound (nothing was saturated at occ 45%).
//
// Block (i-group, h): 8 warps; warp w owns i = i0+w and ALL 8 b's.
//   compute: acc[bp]   = { lt[2bp][lane],   lt[2bp+1][lane]   }  (f32x2)
//            acc[4+bp] = { lt[2bp][lane+32], lt[2bp+1][lane+32] } (lanes<17)
//   gather:  per rj: 1 shfl + per b: broadcast LDS.32 (<=7 banks) + STG.32.
//   Overlay: warp's x slot reused for the lt spill (warp-private, syncwarp).
// grid: (L/8, H) = (128, 8), block: 256.
// ---------------------------------------------------------------------------
__global__ __launch_bounds__(256, 6) void irpe_fused14_kernel(
    const float* __restrict__ x, const float* __restrict__ W,
    const int* __restrict__ rp, float* __restrict__ out)
{
    const int h    = blockIdx.y;
    const int i0   = blockIdx.x * IPB;
    const int tid  = threadIdx.x;
    const int w    = tid >> 5;
    const int lane = tid & 31;
    const int i    = i0 + w;
    const int row_i = i >> 5;
    const int col_i = i & 31;

    __shared__ float Ws[DD * KK + 32];                    // 12.7 KB
    __shared__ __align__(16) float buf[IPB * WSLOT];      // 24 KB: xst / lt overlay

    // Separable index extraction (two tiny rp reads per warp)
    const int cidx  = rp[(size_t)i * LL + row_i * 32 + lane] - 21;  // in [0,6]
    const int rbase = rp[(size_t)i * LL + lane * 32 + col_i] - 3;   // 7*r, lane=rj

    // Stage W[h]: direct coalesced copy
    {
        const float* Wh = W + (size_t)h * DD * KK;
        #pragma unroll
        for (int t = tid; t < DD * KK; t += 256)
            Ws[t] = Wh[t];
    }

    // Stage x transposed with padded rows: buf[ww*768 + d*12 + b]
    #pragma unroll
    for (int t = tid; t < IPB * BB * (DD / 4); t += 256) {
        const int ww = t >> 7;
        const int b  = (t >> 4) & 7;
        const int q  = t & 15;
        float4 v = *(const float4*)(x + ((size_t)(b * HH + h) * LL + i0 + ww) * DD + q * 4);
        float* dst = buf + ww * WSLOT + (q * 4) * XP + b;
        dst[0 * XP] = v.x;
        dst[1 * XP] = v.y;
        dst[2 * XP] = v.z;
        dst[3 * XP] = v.w;
    }
    __syncthreads();

    // Compute lt for all 8 b (b-pairs packed in f32x2)
    unsigned long long acc[8];
    #pragma unroll
    for (int j = 0; j < 8; j++) acc[j] = 0ull;

    const float* xw = buf + w * WSLOT;
    #pragma unroll 16
    for (int d = 0; d < DD; d++) {
        const float w0 = Ws[d * KK + lane];            // conflict-free
        const float w1 = Ws[d * KK + 32 + lane];       // junk lanes>=17, discarded
        unsigned long long wp0, wp1;
        asm("mov.b64 %0, {%1, %1};" : "=l"(wp0) : "f"(w0));
        asm("mov.b64 %0, {%1, %1};" : "=l"(wp1) : "f"(w1));
        const float* xr = xw + d * XP;                 // 16B-aligned row
        const ulonglong2 xq0 = *(const ulonglong2*)(xr);      // {b0b1, b2b3}
        const ulonglong2 xq1 = *(const ulonglong2*)(xr + 4);  // {b4b5, b6b7}
        asm("fma.rn.f32x2 %0, %1, %2, %0;" : "+l"(acc[0]) : "l"(xq0.x), "l"(wp0));
        asm("fma.rn.f32x2 %0, %1, %2, %0;" : "+l"(acc[1]) : "l"(xq0.y), "l"(wp0));
        asm("fma.rn.f32x2 %0, %1, %2, %0;" : "+l"(acc[2]) : "l"(xq1.x), "l"(wp0));
        asm("fma.rn.f32x2 %0, %1, %2, %0;" : "+l"(acc[3]) : "l"(xq1.y), "l"(wp0));
        asm("fma.rn.f32x2 %0, %1, %2, %0;" : "+l"(acc[4]) : "l"(xq0.x), "l"(wp1));
        asm("fma.rn.f32x2 %0, %1, %2, %0;" : "+l"(acc[5]) : "l"(xq0.y), "l"(wp1));
        asm("fma.rn.f32x2 %0, %1, %2, %0;" : "+l"(acc[6]) : "l"(xq1.x), "l"(wp1));
        asm("fma.rn.f32x2 %0, %1, %2, %0;" : "+l"(acc[7]) : "l"(xq1.y), "l"(wp1));
    }

    // Spill lt into the SAME warp-private region (xst now dead): lw[b*49+k]
    float* lw = buf + w * WSLOT;
    __syncwarp();   // all lanes of this warp done reading xst
    #pragma unroll
    for (int bp = 0; bp < 4; bp++) {
        float lo, hi;
        asm("mov.b64 {%0, %1}, %2;" : "=f"(lo), "=f"(hi) : "l"(acc[bp]));
        lw[(2 * bp)     * KK + lane] = lo;
        lw[(2 * bp + 1) * KK + lane] = hi;
        if (lane < KK - 32) {
            asm("mov.b64 {%0, %1}, %2;" : "=f"(lo), "=f"(hi) : "l"(acc[4 + bp]));
            lw[(2 * bp)     * KK + 32 + lane] = lo;
            lw[(2 * bp + 1) * KK + 32 + lane] = hi;
        }
    }
    __syncwarp();

    // Gather + streaming stores.
    // out[b*8+h][i][rj*32+lane] = lw[b*49 + rbase(rj) + cidx(lane)]
    const float* lwc = lw + cidx;
    float* dst = out + ((size_t)h * LL + i) * LL + lane;   // b=0, rj=0 base
    #pragma unroll 4
    for (int rj = 0; rj < 32; rj++) {
        const int rb = __shfl_sync(0xffffffffu, rbase, rj);
        const float* src = lwc + rb;
        #pragma unroll
        for (int b = 0; b < BB; b++) {
            const float v = src[b * KK];                       // broadcast LDS
            __stcs(dst + (size_t)b * (HH * LL * LL), v);       // coalesced STG.32
        }
        dst += 32;
    }
}

// ---------------------------------------------------------------------------
extern "C" void kernel_launch(void* const* d_in, const int* in_sizes, int n_in,
                              void* d_out, int out_size)
{
    const float* x  = (const float*)d_in[0];
    const float* W  = (const float*)d_in[1];
    const int*   rp = (const int*)d_in[2];
    float*       out = (float*)d_out;

    dim3 grid(LL / IPB, HH);
    irpe_fused14_kernel<<<grid, 256>>>(x, W, rp, out);
}